// round 16
// baseline (speedup 1.0000x reference)
#include <cuda_runtime.h>
#include <math_constants.h>
#include <cstdint>

#define BATCH 4
#define SEQ   2048
#define EMB   1024
#define KD    1024

#define BM 128
#define BN 128
#define BKK 32                        // k per stage; 32 floats = 128B row

#define A_STG 16384                   // 128 rows x 128B
#define B_STG 16384
#define SM_B  (3 * A_STG)             // 3-stage A, then 3-stage B
#define SMEM_TOTAL (3 * (A_STG + B_STG))   // 98304; 2 CTAs/SM = 192KB

#define NTHREADS 128                  // 4 warps, 2(M) x 2(N), warp tile 64x64

// ---------------- static device scratch ----------------
__device__ float g_x  [BATCH * SEQ * EMB];
__device__ float g_Wv [EMB * EMB];
__device__ float g_Wqt[EMB * KD];                    // Wq transposed [i][d], tf32
__device__ float g_Wkt[EMB * KD];                    // Wk transposed [i][d], tf32
__device__ float g_Mt [EMB * EMB];                   // Mt[n][k] = sum_d Wk[d][n] Wq[d][k]
__device__ float g_U  [BATCH * SEQ * KD];            // U = x·Mt  (replaces Q; K deleted)
__device__ float g_Vt [BATCH * EMB * SEQ];           // V transposed [b][e][s]
__device__ float g_P  [(long long)BATCH * SEQ * SEQ];// exp(scores), unnormalized
__device__ float g_rowsum[BATCH * SEQ];              // per-row sum of exp

// gate counters, single array (zeroed by prep0 each call -> graph-replay safe)
//  [0,64)   cX    x row-block rounded          ready @1
//  [64]     cT    all W transposes done        ready @128
//  [72,80)  cWv   Wv row-block rounded         ready @1
//  [80,88)  cMrow Mt row-block partials        ready @64 (8 bx x 8 kz)
//  [88,96)  cMR   Mt row-block rounded         ready @1
//  [96,160) cU    U row-block (b*16+bq)        ready @8
//  [160,192)cV    Vt e-block (b*8+ex)          ready @16
//  [192,256)cS    score row-block (b*16+bq)    ready @(bq+1)
__device__ int g_cnt[256];
#define C_X   0
#define C_T   64
#define C_WV  72
#define C_MRW 80
#define C_MR  88
#define C_U   96
#define C_V   160
#define C_S   192

// ---------------- helpers ----------------
__device__ __forceinline__ float tf32r(float x) {
    unsigned r; asm("cvt.rna.tf32.f32 %0, %1;" : "=r"(r) : "f"(x));
    return __uint_as_float(r);
}
__device__ __forceinline__ void cp_async16(uint32_t d, const void* g) {
    asm volatile("cp.async.cg.shared.global [%0], [%1], 16;\n" :: "r"(d), "l"(g));
}
#define CP_COMMIT() asm volatile("cp.async.commit_group;\n" ::: "memory")
#define CP_WAIT(n)  asm volatile("cp.async.wait_group %0;\n" :: "n"(n) : "memory")

__device__ __forceinline__ void ldsm_x4(uint32_t r[4], uint32_t addr) {
    asm volatile("ldmatrix.sync.aligned.m8n8.x4.shared.b16 {%0,%1,%2,%3}, [%4];"
        : "=r"(r[0]), "=r"(r[1]), "=r"(r[2]), "=r"(r[3]) : "r"(addr));
}
__device__ __forceinline__ void mma_tf32(float d[4], const uint32_t a[4], const uint32_t b[2]) {
    asm volatile(
        "mma.sync.aligned.m16n8k8.row.col.f32.tf32.tf32.f32 "
        "{%0,%1,%2,%3}, {%4,%5,%6,%7}, {%8,%9}, {%0,%1,%2,%3};\n"
        : "+f"(d[0]), "+f"(d[1]), "+f"(d[2]), "+f"(d[3])
        : "r"(a[0]), "r"(a[1]), "r"(a[2]), "r"(a[3]), "r"(b[0]), "r"(b[1]));
}
__device__ __forceinline__ int ld_acq(const int* p) {
    int v; asm volatile("ld.global.acquire.gpu.b32 %0, [%1];" : "=r"(v) : "l"(p) : "memory");
    return v;
}
// producer release: all threads fence, then one bumps the counter
__device__ __forceinline__ void release_count(int idx) {
    __threadfence();
    __syncthreads();
    if (threadIdx.x == 0) atomicAdd(&g_cnt[idx], 1);
}
// consumer acquire: tid0 spins (call under "if (tid==0)"), then __syncthreads()
__device__ __forceinline__ void spin1(int idx, int target) {
    while (ld_acq(&g_cnt[idx]) < target) __nanosleep(100);
}

// ---------------- GEMM core: C[m,n] = alpha * A[m,:]·B[n,:], both K-major ----------------
// EPI: 1 = store tf32r(acc)                    (U proj)
//      2 = transposed tf32r store into Vt      (V proj)
//      3 = store acc * (1/rs[row])             (attention out)
//      4 = store masked tf32r(exp(acc*alpha)), atomicAdd row sums into rs  (scores)
//      5 = atomicAdd acc into C (split-K partial, unscaled)                (Mt)
template<int EPI>
__device__ __forceinline__ void gemm_core(
    const float* __restrict__ A, const float* __restrict__ B, float* __restrict__ C,
    int lda, int ldb, long long ldc, int m0, int n0, int kEnd, float alpha,
    float* __restrict__ rs)
{
    extern __shared__ char smraw[];
    const uint32_t sb = (uint32_t)__cvta_generic_to_shared(smraw);
    const int tid  = threadIdx.x;
    const int lane = tid & 31;
    const int warp = tid >> 5;
    const int wm   = warp & 1;
    const int wn   = warp >> 1;
    const int g    = lane >> 2;
    const int tg   = lane & 3;

    const int u   = lane & 7;
    const int j   = lane >> 3;
    const int c0A = j >> 1;
    const int rA  = (j & 1) * 8 + u;
    const int c0B = j & 1;
    const int nB  = (j >> 1) * 8 + u;

    float acc[4][8][4];
    #pragma unroll
    for (int mt = 0; mt < 4; mt++)
        #pragma unroll
        for (int nt = 0; nt < 8; nt++)
            #pragma unroll
            for (int i = 0; i < 4; i++) acc[mt][nt][i] = 0.0f;

    const int nk = kEnd / BKK;

    auto load_stage = [&](int s, int k0) {
        #pragma unroll
        for (int i = 0; i < 8; i++) {
            int c = tid + i * NTHREADS;
            int row = c >> 3, ch = c & 7;
            uint32_t sa = sb + (uint32_t)(s * A_STG + row * 128 + ((ch ^ (row & 7)) * 16));
            cp_async16(sa, &A[(long long)(m0 + row) * lda + k0 + ch * 4]);
        }
        #pragma unroll
        for (int i = 0; i < 8; i++) {
            int c = tid + i * NTHREADS;
            int row = c >> 3, ch = c & 7;
            uint32_t sa = sb + (uint32_t)(SM_B + s * B_STG + row * 128 + ((ch ^ (row & 7)) * 16));
            cp_async16(sa, &B[(long long)(n0 + row) * ldb + k0 + ch * 4]);
        }
    };

    load_stage(0, 0); CP_COMMIT();
    load_stage(1, BKK); CP_COMMIT();

    for (int it = 0; it < nk; ++it) {
        CP_WAIT(1);
        __syncthreads();

        if (it + 2 < nk) load_stage((it + 2) % 3, (it + 2) * BKK);
        CP_COMMIT();

        const uint32_t aBase = sb + (uint32_t)((it % 3) * A_STG);
        const uint32_t bBase = sb + (uint32_t)(SM_B + (it % 3) * B_STG);

        #pragma unroll
        for (int ks = 0; ks < 4; ks++) {
            uint32_t af[4][4], bf[4][4];
            #pragma unroll
            for (int mt = 0; mt < 4; mt++) {
                int row = wm * 64 + mt * 16 + rA;
                ldsm_x4(af[mt], aBase + (uint32_t)(row * 128 + (((c0A + 2 * ks) ^ u) * 16)));
            }
            #pragma unroll
            for (int h = 0; h < 4; h++) {
                int n = wn * 64 + h * 16 + nB;
                ldsm_x4(bf[h], bBase + (uint32_t)(n * 128 + (((c0B + 2 * ks) ^ u) * 16)));
            }
            #pragma unroll
            for (int mt = 0; mt < 4; mt++)
                #pragma unroll
                for (int nt = 0; nt < 8; nt++)
                    mma_tf32(acc[mt][nt], af[mt], &bf[nt >> 1][(nt & 1) * 2]);
        }
    }

    // ---- epilogue ----
    if (EPI == 2) {
        __syncthreads();
        float* sT = (float*)smraw;               // [128 e][stride 132]
        #pragma unroll
        for (int mt = 0; mt < 4; mt++)
            #pragma unroll
            for (int nt = 0; nt < 8; nt++)
                #pragma unroll
                for (int i = 0; i < 4; i++) {
                    int rl = wm * 64 + mt * 16 + g + (i >> 1) * 8;
                    int cl = wn * 64 + nt * 8 + 2 * tg + (i & 1);
                    sT[cl * 132 + rl] = tf32r(acc[mt][nt][i]);
                }
        __syncthreads();
        int b  = m0 >> 11;
        int s0 = m0 & 2047;
        float* dst = C + ((long long)b * EMB + n0) * (long long)SEQ + s0;
        #pragma unroll
        for (int i = 0; i < 32; i++) {
            int idx = tid + i * NTHREADS;
            int er = idx >> 5, sc = (idx & 31) * 4;
            float4 v = *(const float4*)&sT[er * 132 + sc];
            *(float4*)&dst[(long long)er * SEQ + sc] = v;
        }
        __syncthreads();
    } else if (EPI == 4) {
        #pragma unroll
        for (int mt = 0; mt < 4; mt++) {
            const int r0 = m0 + wm * 64 + mt * 16 + g;
            const int r1 = r0 + 8;
            float sum0 = 0.0f, sum1 = 0.0f;
            #pragma unroll
            for (int nt = 0; nt < 8; nt++) {
                const int cc = n0 + wn * 64 + nt * 8 + 2 * tg;
                float e0 = __expf(acc[mt][nt][0] * alpha); if (cc     > r0) e0 = 0.0f;
                float e1 = __expf(acc[mt][nt][1] * alpha); if (cc + 1 > r0) e1 = 0.0f;
                float e2 = __expf(acc[mt][nt][2] * alpha); if (cc     > r1) e2 = 0.0f;
                float e3 = __expf(acc[mt][nt][3] * alpha); if (cc + 1 > r1) e3 = 0.0f;
                sum0 += e0 + e1;
                sum1 += e2 + e3;
                *(float2*)&C[(long long)r0 * ldc + cc] = make_float2(tf32r(e0), tf32r(e1));
                *(float2*)&C[(long long)r1 * ldc + cc] = make_float2(tf32r(e2), tf32r(e3));
            }
            sum0 += __shfl_xor_sync(0xffffffffu, sum0, 1);
            sum0 += __shfl_xor_sync(0xffffffffu, sum0, 2);
            sum1 += __shfl_xor_sync(0xffffffffu, sum1, 1);
            sum1 += __shfl_xor_sync(0xffffffffu, sum1, 2);
            if (tg == 0) {
                atomicAdd(&rs[r0], sum0);
                atomicAdd(&rs[r1], sum1);
            }
        }
    } else if (EPI == 5) {
        #pragma unroll
        for (int mt = 0; mt < 4; mt++) {
            const long long r0 = m0 + wm * 64 + mt * 16 + g;
            const long long r1 = r0 + 8;
            #pragma unroll
            for (int nt = 0; nt < 8; nt++) {
                const int cc = n0 + wn * 64 + nt * 8 + 2 * tg;
                atomicAdd(&C[r0 * ldc + cc],     acc[mt][nt][0]);
                atomicAdd(&C[r0 * ldc + cc + 1], acc[mt][nt][1]);
                atomicAdd(&C[r1 * ldc + cc],     acc[mt][nt][2]);
                atomicAdd(&C[r1 * ldc + cc + 1], acc[mt][nt][3]);
            }
        }
    } else {
        #pragma unroll
        for (int mt = 0; mt < 4; mt++) {
            const long long r0 = m0 + wm * 64 + mt * 16 + g;
            const long long r1 = r0 + 8;
            float inv0 = 1.0f, inv1 = 1.0f;
            if (EPI == 3) { inv0 = 1.0f / rs[r0]; inv1 = 1.0f / rs[r1]; }
            #pragma unroll
            for (int nt = 0; nt < 8; nt++) {
                const int cc = n0 + wn * 64 + nt * 8 + 2 * tg;
                float2 v0, v1;
                if (EPI == 1) {
                    v0 = make_float2(tf32r(acc[mt][nt][0]), tf32r(acc[mt][nt][1]));
                    v1 = make_float2(tf32r(acc[mt][nt][2]), tf32r(acc[mt][nt][3]));
                } else {
                    v0 = make_float2(acc[mt][nt][0] * inv0, acc[mt][nt][1] * inv0);
                    v1 = make_float2(acc[mt][nt][2] * inv1, acc[mt][nt][3] * inv1);
                }
                *(float2*)&C[r0 * ldc + cc] = v0;
                *(float2*)&C[r1 * ldc + cc] = v1;
            }
        }
    }
}

// ---------------- prep0: zero gates, rowsum, Mt (graph-replay safe) ----------------
#define N4_MT (EMB * EMB / 4)              // 256K float4
__global__ void prep0_kernel()
{
    int i = blockIdx.x * blockDim.x + threadIdx.x;
    if (i < 256) g_cnt[i] = 0;
    if (i < BATCH * SEQ / 4) ((float4*)g_rowsum)[i] = make_float4(0.f, 0.f, 0.f, 0.f);
    if (i < N4_MT) ((float4*)g_Mt)[i] = make_float4(0.f, 0.f, 0.f, 0.f);
}

// ---------------- fused main kernel (bid-ordered dependency DAG) ----------------
//  [0,   64): round x row-block (128 rows)                 -> cX[i]
//  [64, 192): transpose Wq/Wk (16 32x32 tiles each)        -> cT
//  [192,200): round Wv row-block                           -> cWv[i]
//  [200,712): Mt split-K (by,bx,kz) gate cT                -> cMrow[by]
//  [712,720): round Mt row-block, gate cMrow[r]@64         -> cMR[r]
//  [720,1232): U(by,bx) gate cX[by], cMR[bx]               -> cU[by]
//  [1232,1744): V(by,bx) gate cX[by], cWv[bx]              -> cV[b*8+bx]
//  [1744,2288): scores gate cU@8, cX[bs-block]             -> cS[b16+bq]
//  [2288,2544): out pair gate cV, cS(bq1), cS(bq2)
#define B_TP 64
#define B_WV 192
#define B_MT 200
#define B_MR 712
#define B_U  720
#define B_V  1232
#define B_S  1744
#define B_O  2288
#define B_END 2544
__global__ __launch_bounds__(NTHREADS, 2)
void main_kernel(const float* __restrict__ x,  const float* __restrict__ Wq,
                 const float* __restrict__ Wk, const float* __restrict__ Wv,
                 float* __restrict__ out)
{
    const int bid = blockIdx.x;
    const int tid = threadIdx.x;

    if (bid < B_TP) {
        // round x rows [bid*128, bid*128+128)
        const float4* src = (const float4*)x + (long long)bid * 32768;
        float4* dst = (float4*)g_x + (long long)bid * 32768;
        for (int i = tid; i < 32768; i += NTHREADS) {
            float4 v = src[i];
            v.x = tf32r(v.x); v.y = tf32r(v.y); v.z = tf32r(v.z); v.w = tf32r(v.w);
            dst[i] = v;
        }
        release_count(C_X + bid);
    } else if (bid < B_WV) {
        // transpose+round: 16 32x32 tiles per block
        extern __shared__ char smraw[];
        float* t = (float*)smraw;               // 32x33 tile buffer
        int k = bid - B_TP;                     // 0..127
        int which = k >> 6;                     // 0 = Wq, 1 = Wk
        const float* src = which ? Wk : Wq;
        float* dst = which ? g_Wkt : g_Wqt;
        int tx = tid & 31, ty = tid >> 5;       // (32,4)
        for (int q = 0; q < 16; q++) {
            int T = (k & 63) * 16 + q;          // tile 0..1023
            int bx = (T & 31) * 32, by = (T >> 5) * 32;
            #pragma unroll
            for (int j = 0; j < 32; j += 4)
                t[(ty + j) * 33 + tx] = tf32r(src[(long long)(by + ty + j) * EMB + bx + tx]);
            __syncthreads();
            #pragma unroll
            for (int j = 0; j < 32; j += 4)
                dst[(long long)(bx + ty + j) * KD + by + tx] = t[tx * 33 + ty + j];
            __syncthreads();
        }
        release_count(C_T);
    } else if (bid < B_MT) {
        // round Wv rows [i*128, ...)
        int i = bid - B_WV;
        const float4* src = (const float4*)Wv + (long long)i * 32768;
        float4* dst = (float4*)g_Wv + (long long)i * 32768;
        for (int c = tid; c < 32768; c += NTHREADS) {
            float4 v = src[c];
            v.x = tf32r(v.x); v.y = tf32r(v.y); v.z = tf32r(v.z); v.w = tf32r(v.w);
            dst[c] = v;
        }
        release_count(C_WV + i);
    } else if (bid < B_MR) {
        // Mt split-K partial
        int idx = bid - B_MT;                   // 0..511
        int kz = idx >> 6, rem = idx & 63;
        int by = rem >> 3, bx = rem & 7;
        if (tid == 0) spin1(C_T, 128);
        __syncthreads();
        gemm_core<5>(g_Wkt + kz * 128, g_Wqt + kz * 128, g_Mt, KD, KD, EMB,
                     by * BM, bx * BN, 128, 1.0f, nullptr);
        release_count(C_MRW + by);
    } else if (bid < B_U) {
        // round Mt row-block r
        int r = bid - B_MR;
        if (tid == 0) spin1(C_MRW + r, 64);
        __syncthreads();
        float4* p = (float4*)g_Mt + (long long)r * 32768;
        for (int c = tid; c < 32768; c += NTHREADS) {
            float4 v = p[c];
            v.x = tf32r(v.x); v.y = tf32r(v.y); v.z = tf32r(v.z); v.w = tf32r(v.w);
            p[c] = v;
        }
        release_count(C_MR + r);
    } else if (bid < B_V) {
        // U = x·Mt
        int idx = bid - B_U;
        int by = idx >> 3, bx = idx & 7;
        if (tid == 0) { spin1(C_X + by, 1); spin1(C_MR + bx, 1); }
        __syncthreads();
        gemm_core<1>(g_x, g_Mt, g_U, EMB, EMB, KD,
                     by * BM, bx * BN, EMB, 1.0f, nullptr);
        release_count(C_U + by);
    } else if (bid < B_S) {
        // Vt = (x·Wv)^T
        int idx = bid - B_V;
        int by = idx >> 3, bx = idx & 7;
        if (tid == 0) { spin1(C_X + by, 1); spin1(C_WV + bx, 1); }
        __syncthreads();
        gemm_core<2>(g_x, g_Wv, g_Vt, EMB, EMB, 0,
                     by * BM, bx * BN, EMB, 1.0f, nullptr);
        release_count(C_V + (by >> 4) * 8 + bx);
    } else if (bid < B_O) {
        // scores (triangular packed)
        int i = bid - B_S;                      // 0..543
        int b = i / 136, t = i - b * 136;
        int bq = 0;
        while ((bq + 1) * (bq + 2) / 2 <= t) bq++;
        int bs = t - bq * (bq + 1) / 2;
        if (tid == 0) { spin1(C_U + b * 16 + bq, 8); spin1(C_X + b * 16 + bs, 1); }
        __syncthreads();
        gemm_core<4>(g_U + (long long)b * SEQ * KD, g_x + (long long)b * SEQ * EMB,
                     g_P + (long long)b * SEQ * SEQ, KD, EMB, SEQ,
                     bq * BM, bs * BN, KD, 0.03125f, g_rowsum + b * SEQ);
        release_count(C_S + b * 16 + bq);
    } else {
        // out antipodal pair
        int jx = bid - B_O;                     // 0..255
        int b = jx >> 6;
        int rem = jx & 63;
        int y = rem >> 3, ex = rem & 7;
        int bq1 = y, bq2 = 15 - y;
        if (tid == 0) {
            spin1(C_V + b * 8 + ex, 16);
            spin1(C_S + b * 16 + bq1, bq1 + 1);
            spin1(C_S + b * 16 + bq2, bq2 + 1);
        }
        __syncthreads();
        const float* Pb = g_P  + (long long)b * SEQ * SEQ;
        const float* Vb = g_Vt + (long long)b * EMB * SEQ;
        float* Ob = out + (long long)b * SEQ * EMB;
        float* rs = g_rowsum + b * SEQ;
        gemm_core<3>(Pb, Vb, Ob, SEQ, SEQ, EMB,
                     bq1 * BM, ex * BN, (bq1 + 1) * BM, 1.0f, rs);
        __syncthreads();
        gemm_core<3>(Pb, Vb, Ob, SEQ, SEQ, EMB,
                     bq2 * BM, ex * BN, (bq2 + 1) * BM, 1.0f, rs);
    }
}

// ---------------- launch ----------------
extern "C" void kernel_launch(void* const* d_in, const int* in_sizes, int n_in,
                              void* d_out, int out_size)
{
    const float* x  = (const float*)d_in[0];
    const float* Wq = (const float*)d_in[1];
    const float* Wk = (const float*)d_in[2];
    const float* Wv = (const float*)d_in[3];
    float* out = (float*)d_out;

    cudaFuncSetAttribute(main_kernel, cudaFuncAttributeMaxDynamicSharedMemorySize, SMEM_TOTAL);

    prep0_kernel<<<(N4_MT + 255) / 256, 256>>>();
    main_kernel<<<B_END, NTHREADS, SMEM_TOTAL>>>(x, Wq, Wk, Wv, out);
}